// round 5
// baseline (speedup 1.0000x reference)
#include <cuda_runtime.h>
#include <cuda_bf16.h>
#include <math.h>
#include <stdint.h>

// ---------------------------------------------------------------------------
// Problem constants
// ---------------------------------------------------------------------------
#define NCAND 100000
#define BQ    1024
#define NT    (NCAND + BQ)       // combined encode rows (candidates then queries)
#define DM    256
#define DH    512
#define NNUM  96
#define MCTX  96
#define RN    (BQ * MCTX)

typedef __nv_bfloat16 bf16;

// ---------------------------------------------------------------------------
// Device scratch
// ---------------------------------------------------------------------------
__device__ float g_h0f [(size_t)NT * DM];
__device__ float g_ckf [(size_t)NT * DM];
__device__ float g_U    [(size_t)RN * DM];
__device__ float g_score[(size_t)BQ * NCAND];
__device__ float g_hnneg[NCAND];
__device__ float g_px [BQ * DM];
__device__ int   g_idx [BQ * MCTX];
__device__ float g_probs[BQ * MCTX];

__device__ bf16 g_xh [(size_t)NT * 128], g_xl [(size_t)NT * 128];
__device__ bf16 g_h0h[(size_t)NT * DM],  g_h0l[(size_t)NT * DM];
__device__ bf16 g_th [(size_t)NT * DH],  g_tl [(size_t)NT * DH];
__device__ bf16 g_lnh[(size_t)NT * DM],  g_lnl[(size_t)NT * DM];
__device__ bf16 g_ckh[(size_t)NT * DM],  g_ckl[(size_t)NT * DM];
__device__ bf16 g_dh [(size_t)RN * DM],  g_dl [(size_t)RN * DM];
__device__ bf16 g_t2h[(size_t)RN * DH],  g_t2l[(size_t)RN * DH];
__device__ bf16 g_pxh[BQ * DM], g_pxl[BQ * DM];
__device__ bf16 g_pth[BQ * DH], g_ptl[BQ * DH];

__device__ bf16 g_winh[256 * 128], g_winl[256 * 128];
__device__ bf16 g_we1h[512 * 256], g_we1l[512 * 256];
__device__ bf16 g_we2h[256 * 512], g_we2l[256 * 512];
__device__ bf16 g_wsh [256 * 256], g_wsl [256 * 256];
__device__ bf16 g_wt1h[512 * 256], g_wt1l[512 * 256];
__device__ bf16 g_wt2h[256 * 512], g_wt2l[256 * 512];
__device__ bf16 g_wp1h[512 * 256], g_wp1l[512 * 256];
__device__ bf16 g_wp2h[256 * 512], g_wp2l[256 * 512];

// ---------------------------------------------------------------------------
// Helpers
// ---------------------------------------------------------------------------
__device__ __forceinline__ uint32_t smem_u32(const void* p) {
    uint32_t a;
    asm("{ .reg .u64 t; cvta.to.shared.u64 t, %1; cvt.u32.u64 %0, t; }" : "=r"(a) : "l"(p));
    return a;
}

__device__ __forceinline__ void cp16(uint32_t dst, const void* src, bool valid) {
    int sz = valid ? 16 : 0;
    asm volatile("cp.async.cg.shared.global [%0], [%1], 16, %2;"
                 :: "r"(dst), "l"(src), "r"(sz));
}
#define CP_COMMIT() asm volatile("cp.async.commit_group;")
#define CP_WAIT(n)  asm volatile("cp.async.wait_group %0;" :: "n"(n))

__device__ __forceinline__ void ldsm4(uint32_t addr, uint32_t& r0, uint32_t& r1,
                                      uint32_t& r2, uint32_t& r3) {
    asm volatile("ldmatrix.sync.aligned.m8n8.x4.shared.b16 {%0,%1,%2,%3}, [%4];"
                 : "=r"(r0), "=r"(r1), "=r"(r2), "=r"(r3) : "r"(addr));
}

__device__ __forceinline__ void mma16816(float* c, const uint32_t* a, const uint32_t* b) {
    asm volatile(
        "mma.sync.aligned.m16n8k16.row.col.f32.bf16.bf16.f32 "
        "{%0,%1,%2,%3}, {%4,%5,%6,%7}, {%8,%9}, {%0,%1,%2,%3};"
        : "+f"(c[0]), "+f"(c[1]), "+f"(c[2]), "+f"(c[3])
        : "r"(a[0]), "r"(a[1]), "r"(a[2]), "r"(a[3]), "r"(b[0]), "r"(b[1]));
}

__device__ __forceinline__ float block_sum_256(float v) {
    __shared__ float sh[8];
    int lane = threadIdx.x & 31, w = threadIdx.x >> 5;
    #pragma unroll
    for (int o = 16; o > 0; o >>= 1) v += __shfl_xor_sync(0xffffffffu, v, o);
    __syncthreads();
    if (lane == 0) sh[w] = v;
    __syncthreads();
    float t = sh[0];
    #pragma unroll
    for (int i = 1; i < 8; i++) t += sh[i];
    return t;
}

__device__ __forceinline__ void split2(float v, bf16& h, bf16& l) {
    h = __float2bfloat16(v);
    l = __float2bfloat16(v - __bfloat162float(h));
}

// ---------------------------------------------------------------------------
// gemm_mma: C[M,N] = op( A[M,Kp] @ B[N,Kp]^T + bias ) via bf16 split-2 HMMA.
// CTA tile 256x128, warp tile 64x64 (4 Mwarps x 2 Nwarps), K-chunk 32,
// 3-stage cp.async pipeline. flags: 1 relu, 2 +res, 4 f32 C, 8 split (Ch,Cl).
// ---------------------------------------------------------------------------
#define LDA 40                           // padded row (elems) -> 80B stride
#define ST_A_ELEM (256 * LDA)
#define ST_B_ELEM (128 * LDA)
#define STAGE_ELEM (ST_A_ELEM + ST_B_ELEM)
#define GEMM_SMEM (3 * STAGE_ELEM * 2)   // 92160 bytes

__global__ __launch_bounds__(256)
void gemm_mma(const bf16* __restrict__ Ah, const bf16* __restrict__ Al,
              const bf16* __restrict__ Bh, const bf16* __restrict__ Bl,
              const float* __restrict__ bias, const float* __restrict__ res,
              float* __restrict__ C, bf16* __restrict__ Ch, bf16* __restrict__ Cl,
              int M, int N, int Kp, int flags)
{
    extern __shared__ __align__(16) bf16 sdyn[];
    __shared__ float sbias[128];

    const int tid  = threadIdx.x;
    const int lane = tid & 31;
    const int wid  = tid >> 5;
    const int wm   = wid & 3;          // 4 warps in M (64 rows each)
    const int wn   = wid >> 2;         // 2 warps in N (64 cols each)
    const int bm   = blockIdx.y * 256;
    const int bn   = blockIdx.x * 128;

    if (tid < 128) {
        int col = bn + tid;
        sbias[tid] = (bias != nullptr && col < N) ? bias[col] : 0.f;
    }

    const uint32_t sBase = smem_u32(sdyn);

    const bf16* segA[3] = {Ah, Ah, Al};
    const bf16* segB[3] = {Bh, Bl, Bh};
    const int nk = Kp >> 5;
    const int NC = 3 * nk;

    float acc[4][8][4];
    #pragma unroll
    for (int t = 0; t < 4; t++)
        #pragma unroll
        for (int j = 0; j < 8; j++)
            #pragma unroll
            for (int e = 0; e < 4; e++) acc[t][j][e] = 0.f;

    auto issue = [&](int c) {
        int seg = c / nk;
        int k0  = (c - seg * nk) << 5;
        const bf16* Ap = segA[seg];
        const bf16* Bp = segB[seg];
        int st = c % 3;
        uint32_t stA = sBase + (uint32_t)(st * STAGE_ELEM * 2);
        uint32_t stB = stA + ST_A_ELEM * 2;
        #pragma unroll
        for (int h = 0; h < 6; h++) {
            int q = tid + h * 256;             // 0..1535
            if (q < 1024) {                     // A: 256 rows x 4 chunks
                int row = q >> 2, sg = q & 3;
                int ar = bm + row; bool av = ar < M; if (!av) ar = 0;
                cp16(stA + (uint32_t)(row * 80 + sg * 16),
                     Ap + (size_t)ar * Kp + k0 + sg * 8, av);
            } else {                            // B: 128 rows x 4 chunks
                int q2 = q - 1024;
                int row = q2 >> 2, sg = q2 & 3;
                int br = bn + row; bool bv = br < N; if (!bv) br = 0;
                cp16(stB + (uint32_t)(row * 80 + sg * 16),
                     Bp + (size_t)br * Kp + k0 + sg * 8, bv);
            }
        }
        CP_COMMIT();
    };

    issue(0);
    issue(1);
    for (int c = 0; c < NC; ++c) {
        if (c + 2 < NC) issue(c + 2);
        else            CP_COMMIT();
        CP_WAIT(2);
        __syncthreads();

        int st = c % 3;
        uint32_t stA = sBase + (uint32_t)(st * STAGE_ELEM * 2);
        uint32_t stB = stA + ST_A_ELEM * 2;
        uint32_t aBase = stA + (uint32_t)((wm * 64) * 80);
        uint32_t bBase = stB + (uint32_t)((wn * 64) * 80);

        #pragma unroll
        for (int ks = 0; ks < 32; ks += 16) {
            uint32_t a[4][4];
            #pragma unroll
            for (int t = 0; t < 4; t++) {
                uint32_t addr = aBase + (uint32_t)((t * 16 + (lane & 15)) * 80
                                                   + (ks + (lane >> 4) * 8) * 2);
                ldsm4(addr, a[t][0], a[t][1], a[t][2], a[t][3]);
            }
            uint32_t b[8][2];
            #pragma unroll
            for (int jp = 0; jp < 4; jp++) {
                int grp = lane >> 3;
                int row = jp * 16 + (grp >> 1) * 8 + (lane & 7);
                int kof = (grp & 1) * 8;
                uint32_t addr = bBase + (uint32_t)(row * 80 + (ks + kof) * 2);
                ldsm4(addr, b[2 * jp][0], b[2 * jp][1], b[2 * jp + 1][0], b[2 * jp + 1][1]);
            }
            #pragma unroll
            for (int t = 0; t < 4; t++)
                #pragma unroll
                for (int j = 0; j < 8; j++)
                    mma16816(acc[t][j], a[t], b[j]);
        }
        __syncthreads();
    }

    // ---- epilogue ----
    int colb = (lane & 3) * 2;
    #pragma unroll
    for (int t = 0; t < 4; t++) {
        int row0 = bm + wm * 64 + t * 16 + (lane >> 2);
        #pragma unroll
        for (int j = 0; j < 8; j++) {
            int col = bn + wn * 64 + j * 8 + colb;
            if (col >= N) continue;
            #pragma unroll
            for (int half = 0; half < 2; half++) {
                int rr = row0 + half * 8;
                if (rr >= M) continue;
                float v0 = acc[t][j][half * 2 + 0];
                float v1 = acc[t][j][half * 2 + 1];
                int cl = col - bn;
                v0 += sbias[cl]; v1 += sbias[cl + 1];
                if (flags & 1) { v0 = fmaxf(v0, 0.f); v1 = fmaxf(v1, 0.f); }
                size_t o = (size_t)rr * N + col;
                if (flags & 2) {
                    float2 r2 = *reinterpret_cast<const float2*>(res + o);
                    v0 += r2.x; v1 += r2.y;
                }
                if (flags & 4) {
                    *reinterpret_cast<float2*>(C + o) = make_float2(v0, v1);
                }
                if (flags & 8) {
                    bf16 h0, l0, h1, l1;
                    split2(v0, h0, l0); split2(v1, h1, l1);
                    *reinterpret_cast<__nv_bfloat162*>(Ch + o) = __nv_bfloat162(h0, h1);
                    *reinterpret_cast<__nv_bfloat162*>(Cl + o) = __nv_bfloat162(l0, l1);
                }
            }
        }
    }
}

// ---------------------------------------------------------------------------
// Grouped weight prep (2 launches instead of 8 -> ncu lands on a GEMM)
// Group3: We1, Wt1, Wp1 : K=256, N=512, Kp=256. grid (512, 3), block 128.
// ---------------------------------------------------------------------------
__global__ void transpose_group3(const float* __restrict__ W0, const float* __restrict__ W1,
                                 const float* __restrict__ W2,
                                 bf16* __restrict__ T0h, bf16* __restrict__ T0l,
                                 bf16* __restrict__ T1h, bf16* __restrict__ T1l,
                                 bf16* __restrict__ T2h, bf16* __restrict__ T2l)
{
    int w = blockIdx.y;
    const float* W = (w == 0) ? W0 : (w == 1) ? W1 : W2;
    bf16* Th = (w == 0) ? T0h : (w == 1) ? T1h : T2h;
    bf16* Tl = (w == 0) ? T0l : (w == 1) ? T1l : T2l;
    int n = blockIdx.x;
    for (int k = threadIdx.x; k < 256; k += 128) {
        float v = W[(size_t)k * 512 + n];
        bf16 h, l; split2(v, h, l);
        Th[(size_t)n * 256 + k] = h;
        Tl[(size_t)n * 256 + k] = l;
    }
}

// Group5: W_in(96->128), We2(512), Ws(256), Wt2(512), Wp2(512); N=256 all.
__global__ void transpose_group5(const float* __restrict__ Win, const float* __restrict__ We2,
                                 const float* __restrict__ Ws,  const float* __restrict__ Wt2,
                                 const float* __restrict__ Wp2,
                                 bf16* __restrict__ T0h, bf16* __restrict__ T0l,
                                 bf16* __restrict__ T1h, bf16* __restrict__ T1l,
                                 bf16* __restrict__ T2h, bf16* __restrict__ T2l,
                                 bf16* __restrict__ T3h, bf16* __restrict__ T3l,
                                 bf16* __restrict__ T4h, bf16* __restrict__ T4l)
{
    int w = blockIdx.y;
    const float* Wt[5] = {Win, We2, Ws, Wt2, Wp2};
    bf16* Tht[5] = {T0h, T1h, T2h, T3h, T4h};
    bf16* Tlt[5] = {T0l, T1l, T2l, T3l, T4l};
    const int Ks [5] = {96, 512, 256, 512, 512};
    const int Kps[5] = {128, 512, 256, 512, 512};
    const float* W = Wt[w];
    bf16* Th = Tht[w];
    bf16* Tl = Tlt[w];
    int K = Ks[w], Kp = Kps[w];
    int n = blockIdx.x;
    for (int k = threadIdx.x; k < Kp; k += 128) {
        float v = (k < K) ? W[(size_t)k * 256 + n] : 0.f;
        bf16 h, l; split2(v, h, l);
        Th[(size_t)n * Kp + k] = h;
        Tl[(size_t)n * Kp + k] = l;
    }
}

// combined input split: rows [0,NCAND)=cand_x, rows [NCAND,NT)=x_num; pad 96->128
__global__ __launch_bounds__(128)
void split_pad96_all(const float* __restrict__ cand, const float* __restrict__ q,
                     bf16* __restrict__ Xh, bf16* __restrict__ Xl)
{
    size_t r = blockIdx.x;
    int t = threadIdx.x;
    const float* src = (r < NCAND) ? (cand + r * NNUM) : (q + (r - NCAND) * NNUM);
    float v = (t < NNUM) ? src[t] : 0.f;
    bf16 h, l; split2(v, h, l);
    Xh[r * 128 + t] = h;
    Xl[r * 128 + t] = l;
}

// ---------------------------------------------------------------------------
// LayerNorm -> split ; half-norm
// ---------------------------------------------------------------------------
__global__ __launch_bounds__(256)
void ln_split(const float* __restrict__ X, const float* __restrict__ g,
              const float* __restrict__ b, bf16* __restrict__ Yh, bf16* __restrict__ Yl)
{
    size_t r = blockIdx.x;
    int tid = threadIdx.x;
    float x = X[r * DM + tid];
    float mu = block_sum_256(x) * (1.f / DM);
    float d = x - mu;
    float var = block_sum_256(d * d) * (1.f / DM);
    float y = d * rsqrtf(var + 1e-5f) * g[tid] + b[tid];
    bf16 h, l; split2(y, h, l);
    Yh[r * DM + tid] = h;
    Yl[r * DM + tid] = l;
}

__global__ __launch_bounds__(256)
void halfnorm_neg(const float* __restrict__ CK, float* __restrict__ hn)
{
    size_t r = blockIdx.x;
    float v = CK[r * DM + threadIdx.x];
    float s = block_sum_256(v * v);
    if (threadIdx.x == 0) hn[r] = -0.5f * s;
}

// ---------------------------------------------------------------------------
// Exact per-row top-96 via radix select + softmax(2*score)
// ---------------------------------------------------------------------------
__device__ __forceinline__ unsigned f2o(float f) {
    unsigned u = __float_as_uint(f);
    return (u & 0x80000000u) ? ~u : (u | 0x80000000u);
}

__global__ __launch_bounds__(256)
void topk_softmax_kernel(const float* __restrict__ score, int N,
                         int* __restrict__ out_idx, float* __restrict__ out_probs)
{
    int row = blockIdx.x;
    const float* s = score + (size_t)row * N;
    int tid = threadIdx.x;
    int lane = tid & 31;

    __shared__ unsigned hist[256];
    __shared__ unsigned sh_prefix;
    __shared__ int sh_kremain;
    __shared__ float vals[MCTX];
    __shared__ int inds[MCTX];
    __shared__ int cnt_gt, cnt_eq;
    __shared__ float evals[MCTX];
    __shared__ float s_max, s_sum;

    if (tid == 0) { sh_prefix = 0u; sh_kremain = MCTX; }

    int nIter = (N + 255) / 256;
    for (int shift = 24; shift >= 0; shift -= 8) {
        hist[tid] = 0;
        __syncthreads();
        unsigned prefix = sh_prefix;
        unsigned mask_hi = (shift == 24) ? 0u : (0xFFFFFFFFu << (shift + 8));
        for (int it = 0; it < nIter; it++) {
            int j = it * 256 + tid;
            bool act = false;
            unsigned bin = 0;
            if (j < N) {
                unsigned u = f2o(s[j]);
                act = ((u & mask_hi) == prefix);
                bin = (u >> shift) & 255u;
            }
            int key = act ? (int)bin : (256 + lane);
            unsigned peers = __match_any_sync(0xffffffffu, key);
            int leader = __ffs(peers) - 1;
            if (act && lane == leader) atomicAdd(&hist[bin], __popc(peers));
        }
        __syncthreads();
        if (tid == 0) {
            int kr = sh_kremain;
            int cum = 0, bsel = 0;
            for (int bb = 255; bb >= 0; bb--) {
                int c = (int)hist[bb];
                if (cum + c >= kr) { bsel = bb; break; }
                cum += c;
            }
            sh_prefix = prefix | ((unsigned)bsel << shift);
            sh_kremain = kr - cum;
        }
        __syncthreads();
    }

    unsigned T = sh_prefix;
    int need = sh_kremain;
    if (tid == 0) { cnt_gt = 0; cnt_eq = 0; }
    __syncthreads();

    for (int j = tid; j < N; j += 256) {
        float f = s[j];
        unsigned u = f2o(f);
        if (u > T) {
            int p = atomicAdd(&cnt_gt, 1);
            vals[p] = f; inds[p] = j;
        } else if (u == T) {
            int p = atomicAdd(&cnt_eq, 1);
            if (p < need) { vals[MCTX - need + p] = f; inds[MCTX - need + p] = j; }
        }
    }
    __syncthreads();

    if (tid == 0) {
        float mx = -1e30f;
        for (int m = 0; m < MCTX; m++) mx = fmaxf(mx, 2.f * vals[m]);
        s_max = mx;
    }
    __syncthreads();
    if (tid < MCTX) evals[tid] = expf(2.f * vals[tid] - s_max);
    __syncthreads();
    if (tid == 0) {
        float sm = 0.f;
        for (int m = 0; m < MCTX; m++) sm += evals[m];
        s_sum = sm;
    }
    __syncthreads();
    if (tid < MCTX) {
        out_probs[row * MCTX + tid] = evals[tid] / s_sum;
        out_idx[row * MCTX + tid]   = inds[tid];
    }
}

// ---------------------------------------------------------------------------
// D split build (query keys are rows NCAND.. of keyf)
// ---------------------------------------------------------------------------
__global__ __launch_bounds__(256)
void build_d_split(const float* __restrict__ keyf, const int* __restrict__ idx,
                   bf16* __restrict__ Dh, bf16* __restrict__ Dl)
{
    int r = blockIdx.x;
    int b = r / MCTX;
    int j = idx[r];
    int t = threadIdx.x;
    float d = keyf[(size_t)(NCAND + b) * DM + t] - keyf[(size_t)j * DM + t];
    bf16 h, l; split2(d, h, l);
    Dh[(size_t)r * DM + t] = h;
    Dl[(size_t)r * DM + t] = l;
}

// ---------------------------------------------------------------------------
// Combine
// ---------------------------------------------------------------------------
__global__ __launch_bounds__(256)
void combine_kernel(const float* __restrict__ h0f, const float* __restrict__ U,
                    const float* __restrict__ probs, const int* __restrict__ idx,
                    const float* __restrict__ cand_y, const float* __restrict__ Wy,
                    const float* __restrict__ by, const float* __restrict__ bt2,
                    float* __restrict__ xout, bf16* __restrict__ Xh, bf16* __restrict__ Xl)
{
    int b = blockIdx.x;
    int tid = threadIdx.x;
    __shared__ float p_s[MCTX];
    __shared__ float py_s[MCTX];
    __shared__ float ybar_s;
    if (tid < MCTX) {
        float p = probs[b * MCTX + tid];
        p_s[tid] = p;
        py_s[tid] = p * cand_y[idx[b * MCTX + tid]];
    }
    __syncthreads();
    if (tid == 0) {
        float yb = 0.f;
        for (int m = 0; m < MCTX; m++) yb += py_s[m];
        ybar_s = yb;
    }
    __syncthreads();
    const float* Ub = U + (size_t)b * MCTX * DM;
    float acc = 0.f;
    #pragma unroll 4
    for (int m = 0; m < MCTX; m++) acc += p_s[m] * Ub[(size_t)m * DM + tid];
    float v = h0f[(size_t)(NCAND + b) * DM + tid] + acc + ybar_s * Wy[tid] + by[tid] + bt2[tid];
    xout[b * DM + tid] = v;
    bf16 hh, ll; split2(v, hh, ll);
    Xh[b * DM + tid] = hh;
    Xl[b * DM + tid] = ll;
}

// ---------------------------------------------------------------------------
// Head
// ---------------------------------------------------------------------------
__global__ __launch_bounds__(256)
void head_kernel(const float* __restrict__ X, const float* __restrict__ g,
                 const float* __restrict__ b, const float* __restrict__ Wh,
                 const float* __restrict__ bh, float* __restrict__ out)
{
    int r = blockIdx.x;
    int tid = threadIdx.x;
    float x = X[(size_t)r * DM + tid];
    float mu = block_sum_256(x) * (1.f / DM);
    float d = x - mu;
    float var = block_sum_256(d * d) * (1.f / DM);
    float y = d * rsqrtf(var + 1e-5f) * g[tid] + b[tid];
    float t = fmaxf(y, 0.f) * Wh[tid];
    float tot = block_sum_256(t);
    if (tid == 0) out[r] = tot + bh[0];
}

// ---------------------------------------------------------------------------
// Launcher
// ---------------------------------------------------------------------------
#define GETSYM(var, sym) cudaGetSymbolAddress((void**)&(var), sym)

extern "C" void kernel_launch(void* const* d_in, const int* in_sizes, int n_in,
                              void* d_out, int out_size)
{
    const float* x_num  = (const float*)d_in[0];
    const float* cand_x = (const float*)d_in[1];
    const float* cand_y = (const float*)d_in[2];
    int off = (n_in >= 27) ? 1 : 0;
    int i = 3 + off;
    const float* W_in = (const float*)d_in[i++]; const float* b_in = (const float*)d_in[i++];
    const float* We1  = (const float*)d_in[i++]; const float* be1  = (const float*)d_in[i++];
    const float* We2  = (const float*)d_in[i++]; const float* be2  = (const float*)d_in[i++];
    const float* g_m  = (const float*)d_in[i++]; const float* b_m  = (const float*)d_in[i++];
    const float* Ws   = (const float*)d_in[i++]; const float* bs   = (const float*)d_in[i++];
    const float* Wy   = (const float*)d_in[i++]; const float* by   = (const float*)d_in[i++];
    const float* Wt1  = (const float*)d_in[i++];
    const float* Wt2  = (const float*)d_in[i++]; const float* bt2  = (const float*)d_in[i++];
    const float* Wp1  = (const float*)d_in[i++]; const float* bp1  = (const float*)d_in[i++];
    const float* Wp2  = (const float*)d_in[i++]; const float* bp2  = (const float*)d_in[i++];
    const float* g_h  = (const float*)d_in[i++]; const float* b_h  = (const float*)d_in[i++];
    const float* Wh   = (const float*)d_in[i++]; const float* bh   = (const float*)d_in[i++];
    float* out = (float*)d_out;

    cudaFuncSetAttribute(gemm_mma, cudaFuncAttributeMaxDynamicSharedMemorySize, GEMM_SMEM);

    float *h0f, *ckf, *U, *score, *hnneg, *px, *probs;
    int* idxp;
    GETSYM(h0f, g_h0f); GETSYM(ckf, g_ckf); GETSYM(U, g_U); GETSYM(score, g_score);
    GETSYM(hnneg, g_hnneg); GETSYM(px, g_px);
    GETSYM(idxp, g_idx); GETSYM(probs, g_probs);

    bf16 *xh,*xl,*h0h,*h0l,*th,*tl,*lnh,*lnl,*ckh,*ckl;
    bf16 *dh,*dl,*t2h,*t2l,*pxh,*pxl,*pth,*ptl;
    GETSYM(xh, g_xh); GETSYM(xl, g_xl);
    GETSYM(h0h, g_h0h); GETSYM(h0l, g_h0l); GETSYM(th, g_th);  GETSYM(tl, g_tl);
    GETSYM(lnh, g_lnh); GETSYM(lnl, g_lnl); GETSYM(ckh, g_ckh); GETSYM(ckl, g_ckl);
    GETSYM(dh, g_dh); GETSYM(dl, g_dl); GETSYM(t2h, g_t2h); GETSYM(t2l, g_t2l);
    GETSYM(pxh, g_pxh); GETSYM(pxl, g_pxl); GETSYM(pth, g_pth); GETSYM(ptl, g_ptl);

    bf16 *winh,*winl,*we1h,*we1l,*we2h,*we2l,*wsh,*wsl,*wt1h,*wt1l,*wt2h,*wt2l,*wp1h,*wp1l,*wp2h,*wp2l;
    GETSYM(winh, g_winh); GETSYM(winl, g_winl);
    GETSYM(we1h, g_we1h); GETSYM(we1l, g_we1l);
    GETSYM(we2h, g_we2h); GETSYM(we2l, g_we2l);
    GETSYM(wsh, g_wsh);   GETSYM(wsl, g_wsl);
    GETSYM(wt1h, g_wt1h); GETSYM(wt1l, g_wt1l);
    GETSYM(wt2h, g_wt2h); GETSYM(wt2l, g_wt2l);
    GETSYM(wp1h, g_wp1h); GETSYM(wp1l, g_wp1l);
    GETSYM(wp2h, g_wp2h); GETSYM(wp2l, g_wp2l);

    // [0..2] prep (3 launches so ncu -s 5 lands on a big GEMM)
    transpose_group3<<<dim3(512, 3), 128>>>(We1, Wt1, Wp1,
                                            we1h, we1l, wt1h, wt1l, wp1h, wp1l);
    transpose_group5<<<dim3(256, 5), 128>>>(W_in, We2, Ws, Wt2, Wp2,
                                            winh, winl, we2h, we2l, wsh, wsl,
                                            wt2h, wt2l, wp2h, wp2l);
    split_pad96_all<<<NT, 128>>>(cand_x, x_num, xh, xl);

    const int GT = (NT + 255) / 256;     // 395 M-blocks for combined encode

    // [3..5] combined encode (candidates + queries)
    gemm_mma<<<dim3(2, GT), 256, GEMM_SMEM>>>(xh, xl, winh, winl, b_in, nullptr,
                                              h0f, h0h, h0l, NT, 256, 128, 4 | 8);
    gemm_mma<<<dim3(4, GT), 256, GEMM_SMEM>>>(h0h, h0l, we1h, we1l, be1, nullptr,
                                              nullptr, th, tl, NT, 512, 256, 1 | 8);
    gemm_mma<<<dim3(2, GT), 256, GEMM_SMEM>>>(th, tl, we2h, we2l, be2, h0f,
                                              h0f, nullptr, nullptr, NT, 256, 512, 2 | 4);
    ln_split<<<NT, 256>>>(h0f, g_m, b_m, lnh, lnl);
    gemm_mma<<<dim3(2, GT), 256, GEMM_SMEM>>>(lnh, lnl, wsh, wsl, bs, nullptr,
                                              ckf, ckh, ckl, NT, 256, 256, 4 | 8);
    halfnorm_neg<<<NCAND, 256>>>(ckf, hnneg);

    // similarity scores: A = query keys (rows NCAND..), B = candidate keys
    gemm_mma<<<dim3(782, 4), 256, GEMM_SMEM>>>(
        ckh + (size_t)NCAND * DM, ckl + (size_t)NCAND * DM, ckh, ckl, hnneg, nullptr,
        score, nullptr, nullptr, BQ, NCAND, 256, 4);

    topk_softmax_kernel<<<BQ, 256>>>(score, NCAND, idxp, probs);
    build_d_split<<<RN, 256>>>(ckf, idxp, dh, dl);

    // value MLP
    gemm_mma<<<dim3(4, 384), 256, GEMM_SMEM>>>(dh, dl, wt1h, wt1l, nullptr, nullptr,
                                               nullptr, t2h, t2l, RN, 512, 256, 1 | 8);
    gemm_mma<<<dim3(2, 384), 256, GEMM_SMEM>>>(t2h, t2l, wt2h, wt2l, nullptr, nullptr,
                                               U, nullptr, nullptr, RN, 256, 512, 4);

    combine_kernel<<<BQ, 256>>>(h0f, U, probs, idxp, cand_y, Wy, by, bt2, px, pxh, pxl);

    // predictor + head
    gemm_mma<<<dim3(4, 4), 256, GEMM_SMEM>>>(pxh, pxl, wp1h, wp1l, bp1, nullptr,
                                             nullptr, pth, ptl, BQ, 512, 256, 1 | 8);
    gemm_mma<<<dim3(2, 4), 256, GEMM_SMEM>>>(pth, ptl, wp2h, wp2l, bp2, px,
                                             px, nullptr, nullptr, BQ, 256, 512, 2 | 4);
    head_kernel<<<BQ, 256>>>(px, g_h, b_h, Wh, bh, out);

    (void)in_sizes; (void)out_size;
}

// round 6
// speedup vs baseline: 1.1374x; 1.1374x over previous
#include <cuda_runtime.h>
#include <cuda_bf16.h>
#include <math.h>
#include <stdint.h>

// ---------------------------------------------------------------------------
// Problem constants
// ---------------------------------------------------------------------------
#define NCAND 100000
#define BQ    1024
#define NT    (NCAND + BQ)
#define DM    256
#define DH    512
#define NNUM  96
#define MCTX  96
#define RN    (BQ * MCTX)

typedef __nv_bfloat16 bf16;

// ---------------------------------------------------------------------------
// Device scratch
// ---------------------------------------------------------------------------
__device__ float g_h0f [(size_t)NT * DM];
__device__ float g_ckf [(size_t)NT * DM];
__device__ float g_U    [(size_t)RN * DM];
__device__ float g_score[(size_t)BQ * NCAND];
__device__ float g_hnneg[NCAND];
__device__ float g_px [BQ * DM];
__device__ int   g_idx [BQ * MCTX];
__device__ float g_probs[BQ * MCTX];

__device__ bf16 g_xh [(size_t)NT * 128], g_xl [(size_t)NT * 128];
__device__ bf16 g_h0h[(size_t)NT * DM],  g_h0l[(size_t)NT * DM];
__device__ bf16 g_th [(size_t)NT * DH],  g_tl [(size_t)NT * DH];
__device__ bf16 g_lnh[(size_t)NT * DM],  g_lnl[(size_t)NT * DM];
__device__ bf16 g_ckh[(size_t)NT * DM],  g_ckl[(size_t)NT * DM];
__device__ bf16 g_dh [(size_t)RN * DM],  g_dl [(size_t)RN * DM];
__device__ bf16 g_t2h[(size_t)RN * DH],  g_t2l[(size_t)RN * DH];
__device__ bf16 g_pxh[BQ * DM], g_pxl[BQ * DM];
__device__ bf16 g_pth[BQ * DH], g_ptl[BQ * DH];

__device__ bf16 g_winh[256 * 128], g_winl[256 * 128];
__device__ bf16 g_we1h[512 * 256], g_we1l[512 * 256];
__device__ bf16 g_we2h[256 * 512], g_we2l[256 * 512];
__device__ bf16 g_wsh [256 * 256], g_wsl [256 * 256];
__device__ bf16 g_wt1h[512 * 256], g_wt1l[512 * 256];
__device__ bf16 g_wt2h[256 * 512], g_wt2l[256 * 512];
__device__ bf16 g_wp1h[512 * 256], g_wp1l[512 * 256];
__device__ bf16 g_wp2h[256 * 512], g_wp2l[256 * 512];

// ---------------------------------------------------------------------------
// Helpers
// ---------------------------------------------------------------------------
__device__ __forceinline__ uint32_t smem_u32(const void* p) {
    uint32_t a;
    asm("{ .reg .u64 t; cvta.to.shared.u64 t, %1; cvt.u32.u64 %0, t; }" : "=r"(a) : "l"(p));
    return a;
}

__device__ __forceinline__ void cp16(uint32_t dst, const void* src, bool valid) {
    int sz = valid ? 16 : 0;
    asm volatile("cp.async.cg.shared.global [%0], [%1], 16, %2;"
                 :: "r"(dst), "l"(src), "r"(sz));
}
#define CP_COMMIT() asm volatile("cp.async.commit_group;")
#define CP_WAIT(n)  asm volatile("cp.async.wait_group %0;" :: "n"(n))

__device__ __forceinline__ void ldsm4(uint32_t addr, uint32_t& r0, uint32_t& r1,
                                      uint32_t& r2, uint32_t& r3) {
    asm volatile("ldmatrix.sync.aligned.m8n8.x4.shared.b16 {%0,%1,%2,%3}, [%4];"
                 : "=r"(r0), "=r"(r1), "=r"(r2), "=r"(r3) : "r"(addr));
}

__device__ __forceinline__ void mma16816(float* c, const uint32_t* a, const uint32_t* b) {
    asm volatile(
        "mma.sync.aligned.m16n8k16.row.col.f32.bf16.bf16.f32 "
        "{%0,%1,%2,%3}, {%4,%5,%6,%7}, {%8,%9}, {%0,%1,%2,%3};"
        : "+f"(c[0]), "+f"(c[1]), "+f"(c[2]), "+f"(c[3])
        : "r"(a[0]), "r"(a[1]), "r"(a[2]), "r"(a[3]), "r"(b[0]), "r"(b[1]));
}

__device__ __forceinline__ float block_sum_256(float v) {
    __shared__ float sh[8];
    int lane = threadIdx.x & 31, w = threadIdx.x >> 5;
    #pragma unroll
    for (int o = 16; o > 0; o >>= 1) v += __shfl_xor_sync(0xffffffffu, v, o);
    __syncthreads();
    if (lane == 0) sh[w] = v;
    __syncthreads();
    float t = sh[0];
    #pragma unroll
    for (int i = 1; i < 8; i++) t += sh[i];
    return t;
}

__device__ __forceinline__ void split2(float v, bf16& h, bf16& l) {
    h = __float2bfloat16(v);
    l = __float2bfloat16(v - __bfloat162float(h));
}

// ---------------------------------------------------------------------------
// gemm_mma: C[M,N] = op( A[M,Kp] @ B[N,Kp]^T + bias ) via bf16 split-2 HMMA.
// CTA tile 128x128, warp tile 32x64 (4Mx2N warps), K-chunk 32.
// 4-stage cp.async ring, lookahead 2, ONE barrier per chunk.
// __launch_bounds__(256,2) caps regs at 128 -> 2 CTAs/SM.
// flags: 1 relu, 2 +res, 4 write f32 C, 8 write split (Ch,Cl)
// ---------------------------------------------------------------------------
#define LDA 40                           // padded row (elems) -> 80B stride
#define STG_ELEM (128 * LDA)             // per operand per stage
#define STAGE_BYTES (2 * STG_ELEM * 2)   // A+B per stage = 20480 B
#define NSTAGE 4
#define GEMM_SMEM (NSTAGE * STAGE_BYTES) // 81920 B

__global__ __launch_bounds__(256, 2)
void gemm_mma(const bf16* __restrict__ Ah, const bf16* __restrict__ Al,
              const bf16* __restrict__ Bh, const bf16* __restrict__ Bl,
              const float* __restrict__ bias, const float* __restrict__ res,
              float* __restrict__ C, bf16* __restrict__ Ch, bf16* __restrict__ Cl,
              int M, int N, int Kp, int flags)
{
    extern __shared__ __align__(16) bf16 sdyn[];
    __shared__ float sbias[128];

    const int tid  = threadIdx.x;
    const int lane = tid & 31;
    const int wid  = tid >> 5;
    const int wm   = wid & 3;          // 4 warps in M (32 rows each)
    const int wn   = wid >> 2;         // 2 warps in N (64 cols each)
    const int bm   = blockIdx.y * 128;
    const int bn   = blockIdx.x * 128;

    if (tid < 128) {
        int col = bn + tid;
        sbias[tid] = (bias != nullptr && col < N) ? bias[col] : 0.f;
    }

    const uint32_t sBase = smem_u32(sdyn);

    const bf16* segA[3] = {Ah, Ah, Al};
    const bf16* segB[3] = {Bh, Bl, Bh};
    const int nk = Kp >> 5;
    const int NC = 3 * nk;

    float acc[2][8][4];
    #pragma unroll
    for (int t = 0; t < 2; t++)
        #pragma unroll
        for (int j = 0; j < 8; j++)
            #pragma unroll
            for (int e = 0; e < 4; e++) acc[t][j][e] = 0.f;

    auto issue = [&](int c) {
        int seg = c / nk;
        int k0  = (c - seg * nk) << 5;
        const bf16* Ap = segA[seg];
        const bf16* Bp = segB[seg];
        int st = c & (NSTAGE - 1);
        uint32_t stA = sBase + (uint32_t)(st * STAGE_BYTES);
        uint32_t stB = stA + STG_ELEM * 2;
        #pragma unroll
        for (int h = 0; h < 2; h++) {
            int q   = tid + h * 256;       // 0..511
            int row = q >> 2;
            int sg  = q & 3;
            uint32_t off = (uint32_t)(row * 80 + sg * 16);
            int ar = bm + row; bool av = ar < M; if (!av) ar = 0;
            cp16(stA + off, Ap + (size_t)ar * Kp + k0 + sg * 8, av);
            int br = bn + row; bool bv = br < N; if (!bv) br = 0;
            cp16(stB + off, Bp + (size_t)br * Kp + k0 + sg * 8, bv);
        }
        CP_COMMIT();
    };

    issue(0);
    issue(1);
    for (int c = 0; c < NC; ++c) {
        // write stage (c+2)%4; other warps read at most stages (c-1)%4, c%4
        // -> distance 3 / 2, never equal: safe with a single barrier below.
        if (c + 2 < NC) issue(c + 2);
        else            CP_COMMIT();
        CP_WAIT(2);
        __syncthreads();

        int st = c & (NSTAGE - 1);
        uint32_t stA = sBase + (uint32_t)(st * STAGE_BYTES);
        uint32_t stB = stA + STG_ELEM * 2;
        uint32_t aBase = stA + (uint32_t)((wm * 32) * 80);
        uint32_t bBase = stB + (uint32_t)((wn * 64) * 80);

        #pragma unroll
        for (int ks = 0; ks < 32; ks += 16) {
            uint32_t a[2][4];
            #pragma unroll
            for (int t = 0; t < 2; t++) {
                uint32_t addr = aBase + (uint32_t)((t * 16 + (lane & 15)) * 80
                                                   + (ks + (lane >> 4) * 8) * 2);
                ldsm4(addr, a[t][0], a[t][1], a[t][2], a[t][3]);
            }
            uint32_t b[8][2];
            #pragma unroll
            for (int jp = 0; jp < 4; jp++) {
                int grp = lane >> 3;
                int row = jp * 16 + (grp >> 1) * 8 + (lane & 7);
                int kof = (grp & 1) * 8;
                uint32_t addr = bBase + (uint32_t)(row * 80 + (ks + kof) * 2);
                ldsm4(addr, b[2 * jp][0], b[2 * jp][1], b[2 * jp + 1][0], b[2 * jp + 1][1]);
            }
            #pragma unroll
            for (int t = 0; t < 2; t++)
                #pragma unroll
                for (int j = 0; j < 8; j++)
                    mma16816(acc[t][j], a[t], b[j]);
        }
        // no trailing barrier: next iteration's writes go to a disjoint stage
    }

    // ---- epilogue ----
    int colb = (lane & 3) * 2;
    #pragma unroll
    for (int t = 0; t < 2; t++) {
        int row0 = bm + wm * 32 + t * 16 + (lane >> 2);
        #pragma unroll
        for (int j = 0; j < 8; j++) {
            int col = bn + wn * 64 + j * 8 + colb;
            if (col >= N) continue;
            #pragma unroll
            for (int half = 0; half < 2; half++) {
                int rr = row0 + half * 8;
                if (rr >= M) continue;
                float v0 = acc[t][j][half * 2 + 0];
                float v1 = acc[t][j][half * 2 + 1];
                int cl = col - bn;
                v0 += sbias[cl]; v1 += sbias[cl + 1];
                if (flags & 1) { v0 = fmaxf(v0, 0.f); v1 = fmaxf(v1, 0.f); }
                size_t o = (size_t)rr * N + col;
                if (flags & 2) {
                    float2 r2 = *reinterpret_cast<const float2*>(res + o);
                    v0 += r2.x; v1 += r2.y;
                }
                if (flags & 4) {
                    *reinterpret_cast<float2*>(C + o) = make_float2(v0, v1);
                }
                if (flags & 8) {
                    bf16 h0, l0, h1, l1;
                    split2(v0, h0, l0); split2(v1, h1, l1);
                    *reinterpret_cast<__nv_bfloat162*>(Ch + o) = __nv_bfloat162(h0, h1);
                    *reinterpret_cast<__nv_bfloat162*>(Cl + o) = __nv_bfloat162(l0, l1);
                }
            }
        }
    }
}

// ---------------------------------------------------------------------------
// Grouped weight prep
// ---------------------------------------------------------------------------
__global__ void transpose_group3(const float* __restrict__ W0, const float* __restrict__ W1,
                                 const float* __restrict__ W2,
                                 bf16* __restrict__ T0h, bf16* __restrict__ T0l,
                                 bf16* __restrict__ T1h, bf16* __restrict__ T1l,
                                 bf16* __restrict__ T2h, bf16* __restrict__ T2l)
{
    int w = blockIdx.y;
    const float* W = (w == 0) ? W0 : (w == 1) ? W1 : W2;
    bf16* Th = (w == 0) ? T0h : (w == 1) ? T1h : T2h;
    bf16* Tl = (w == 0) ? T0l : (w == 1) ? T1l : T2l;
    int n = blockIdx.x;
    for (int k = threadIdx.x; k < 256; k += 128) {
        float v = W[(size_t)k * 512 + n];
        bf16 h, l; split2(v, h, l);
        Th[(size_t)n * 256 + k] = h;
        Tl[(size_t)n * 256 + k] = l;
    }
}

__global__ void transpose_group5(const float* __restrict__ Win, const float* __restrict__ We2,
                                 const float* __restrict__ Ws,  const float* __restrict__ Wt2,
                                 const float* __restrict__ Wp2,
                                 bf16* __restrict__ T0h, bf16* __restrict__ T0l,
                                 bf16* __restrict__ T1h, bf16* __restrict__ T1l,
                                 bf16* __restrict__ T2h, bf16* __restrict__ T2l,
                                 bf16* __restrict__ T3h, bf16* __restrict__ T3l,
                                 bf16* __restrict__ T4h, bf16* __restrict__ T4l)
{
    int w = blockIdx.y;
    const float* Wt[5] = {Win, We2, Ws, Wt2, Wp2};
    bf16* Tht[5] = {T0h, T1h, T2h, T3h, T4h};
    bf16* Tlt[5] = {T0l, T1l, T2l, T3l, T4l};
    const int Ks [5] = {96, 512, 256, 512, 512};
    const int Kps[5] = {128, 512, 256, 512, 512};
    const float* W = Wt[w];
    bf16* Th = Tht[w];
    bf16* Tl = Tlt[w];
    int K = Ks[w], Kp = Kps[w];
    int n = blockIdx.x;
    for (int k = threadIdx.x; k < Kp; k += 128) {
        float v = (k < K) ? W[(size_t)k * 256 + n] : 0.f;
        bf16 h, l; split2(v, h, l);
        Th[(size_t)n * Kp + k] = h;
        Tl[(size_t)n * Kp + k] = l;
    }
}

__global__ __launch_bounds__(128)
void split_pad96_all(const float* __restrict__ cand, const float* __restrict__ q,
                     bf16* __restrict__ Xh, bf16* __restrict__ Xl)
{
    size_t r = blockIdx.x;
    int t = threadIdx.x;
    const float* src = (r < NCAND) ? (cand + r * NNUM) : (q + (r - NCAND) * NNUM);
    float v = (t < NNUM) ? src[t] : 0.f;
    bf16 h, l; split2(v, h, l);
    Xh[r * 128 + t] = h;
    Xl[r * 128 + t] = l;
}

// ---------------------------------------------------------------------------
// LayerNorm -> split ; half-norm
// ---------------------------------------------------------------------------
__global__ __launch_bounds__(256)
void ln_split(const float* __restrict__ X, const float* __restrict__ g,
              const float* __restrict__ b, bf16* __restrict__ Yh, bf16* __restrict__ Yl)
{
    size_t r = blockIdx.x;
    int tid = threadIdx.x;
    float x = X[r * DM + tid];
    float mu = block_sum_256(x) * (1.f / DM);
    float d = x - mu;
    float var = block_sum_256(d * d) * (1.f / DM);
    float y = d * rsqrtf(var + 1e-5f) * g[tid] + b[tid];
    bf16 h, l; split2(y, h, l);
    Yh[r * DM + tid] = h;
    Yl[r * DM + tid] = l;
}

__global__ __launch_bounds__(256)
void halfnorm_neg(const float* __restrict__ CK, float* __restrict__ hn)
{
    size_t r = blockIdx.x;
    float v = CK[r * DM + threadIdx.x];
    float s = block_sum_256(v * v);
    if (threadIdx.x == 0) hn[r] = -0.5f * s;
}

// ---------------------------------------------------------------------------
// Exact per-row top-96 via radix select + softmax(2*score)
// ---------------------------------------------------------------------------
__device__ __forceinline__ unsigned f2o(float f) {
    unsigned u = __float_as_uint(f);
    return (u & 0x80000000u) ? ~u : (u | 0x80000000u);
}

__global__ __launch_bounds__(256)
void topk_softmax_kernel(const float* __restrict__ score, int N,
                         int* __restrict__ out_idx, float* __restrict__ out_probs)
{
    int row = blockIdx.x;
    const float* s = score + (size_t)row * N;
    int tid = threadIdx.x;
    int lane = tid & 31;

    __shared__ unsigned hist[256];
    __shared__ unsigned sh_prefix;
    __shared__ int sh_kremain;
    __shared__ float vals[MCTX];
    __shared__ int inds[MCTX];
    __shared__ int cnt_gt, cnt_eq;
    __shared__ float evals[MCTX];
    __shared__ float s_max, s_sum;

    if (tid == 0) { sh_prefix = 0u; sh_kremain = MCTX; }

    int nIter = (N + 255) / 256;
    for (int shift = 24; shift >= 0; shift -= 8) {
        hist[tid] = 0;
        __syncthreads();
        unsigned prefix = sh_prefix;
        unsigned mask_hi = (shift == 24) ? 0u : (0xFFFFFFFFu << (shift + 8));
        for (int it = 0; it < nIter; it++) {
            int j = it * 256 + tid;
            bool act = false;
            unsigned bin = 0;
            if (j < N) {
                unsigned u = f2o(s[j]);
                act = ((u & mask_hi) == prefix);
                bin = (u >> shift) & 255u;
            }
            int key = act ? (int)bin : (256 + lane);
            unsigned peers = __match_any_sync(0xffffffffu, key);
            int leader = __ffs(peers) - 1;
            if (act && lane == leader) atomicAdd(&hist[bin], __popc(peers));
        }
        __syncthreads();
        if (tid == 0) {
            int kr = sh_kremain;
            int cum = 0, bsel = 0;
            for (int bb = 255; bb >= 0; bb--) {
                int c = (int)hist[bb];
                if (cum + c >= kr) { bsel = bb; break; }
                cum += c;
            }
            sh_prefix = prefix | ((unsigned)bsel << shift);
            sh_kremain = kr - cum;
        }
        __syncthreads();
    }

    unsigned T = sh_prefix;
    int need = sh_kremain;
    if (tid == 0) { cnt_gt = 0; cnt_eq = 0; }
    __syncthreads();

    for (int j = tid; j < N; j += 256) {
        float f = s[j];
        unsigned u = f2o(f);
        if (u > T) {
            int p = atomicAdd(&cnt_gt, 1);
            vals[p] = f; inds[p] = j;
        } else if (u == T) {
            int p = atomicAdd(&cnt_eq, 1);
            if (p < need) { vals[MCTX - need + p] = f; inds[MCTX - need + p] = j; }
        }
    }
    __syncthreads();

    if (tid == 0) {
        float mx = -1e30f;
        for (int m = 0; m < MCTX; m++) mx = fmaxf(mx, 2.f * vals[m]);
        s_max = mx;
    }
    __syncthreads();
    if (tid < MCTX) evals[tid] = expf(2.f * vals[tid] - s_max);
    __syncthreads();
    if (tid == 0) {
        float sm = 0.f;
        for (int m = 0; m < MCTX; m++) sm += evals[m];
        s_sum = sm;
    }
    __syncthreads();
    if (tid < MCTX) {
        out_probs[row * MCTX + tid] = evals[tid] / s_sum;
        out_idx[row * MCTX + tid]   = inds[tid];
    }
}

// ---------------------------------------------------------------------------
// D split build
// ---------------------------------------------------------------------------
__global__ __launch_bounds__(256)
void build_d_split(const float* __restrict__ keyf, const int* __restrict__ idx,
                   bf16* __restrict__ Dh, bf16* __restrict__ Dl)
{
    int r = blockIdx.x;
    int b = r / MCTX;
    int j = idx[r];
    int t = threadIdx.x;
    float d = keyf[(size_t)(NCAND + b) * DM + t] - keyf[(size_t)j * DM + t];
    bf16 h, l; split2(d, h, l);
    Dh[(size_t)r * DM + t] = h;
    Dl[(size_t)r * DM + t] = l;
}

// ---------------------------------------------------------------------------
// Combine
// ---------------------------------------------------------------------------
__global__ __launch_bounds__(256)
void combine_kernel(const float* __restrict__ h0f, const float* __restrict__ U,
                    const float* __restrict__ probs, const int* __restrict__ idx,
                    const float* __restrict__ cand_y, const float* __restrict__ Wy,
                    const float* __restrict__ by, const float* __restrict__ bt2,
                    float* __restrict__ xout, bf16* __restrict__ Xh, bf16* __restrict__ Xl)
{
    int b = blockIdx.x;
    int tid = threadIdx.x;
    __shared__ float p_s[MCTX];
    __shared__ float py_s[MCTX];
    __shared__ float ybar_s;
    if (tid < MCTX) {
        float p = probs[b * MCTX + tid];
        p_s[tid] = p;
        py_s[tid] = p * cand_y[idx[b * MCTX + tid]];
    }
    __syncthreads();
    if (tid == 0) {
        float yb = 0.f;
        for (int m = 0; m < MCTX; m++) yb += py_s[m];
        ybar_s = yb;
    }
    __syncthreads();
    const float* Ub = U + (size_t)b * MCTX * DM;
    float acc = 0.f;
    #pragma unroll 4
    for (int m = 0; m < MCTX; m++) acc += p_s[m] * Ub[(size_t)m * DM + tid];
    float v = h0f[(size_t)(NCAND + b) * DM + tid] + acc + ybar_s * Wy[tid] + by[tid] + bt2[tid];
    xout[b * DM + tid] = v;
    bf16 hh, ll; split2(v, hh, ll);
    Xh[b * DM + tid] = hh;
    Xl[b * DM + tid] = ll;
}

// ---------------------------------------------------------------------------
// Head
// ---------------------------------------------------------------------------
__global__ __launch_bounds__(256)
void head_kernel(const float* __restrict__ X, const float* __restrict__ g,
                 const float* __restrict__ b, const float* __restrict__ Wh,
                 const float* __restrict__ bh, float* __restrict__ out)
{
    int r = blockIdx.x;
    int tid = threadIdx.x;
    float x = X[(size_t)r * DM + tid];
    float mu = block_sum_256(x) * (1.f / DM);
    float d = x - mu;
    float var = block_sum_256(d * d) * (1.f / DM);
    float y = d * rsqrtf(var + 1e-5f) * g[tid] + b[tid];
    float t = fmaxf(y, 0.f) * Wh[tid];
    float tot = block_sum_256(t);
    if (tid == 0) out[r] = tot + bh[0];
}

// ---------------------------------------------------------------------------
// Launcher
// ---------------------------------------------------------------------------
#define GETSYM(var, sym) cudaGetSymbolAddress((void**)&(var), sym)

extern "C" void kernel_launch(void* const* d_in, const int* in_sizes, int n_in,
                              void* d_out, int out_size)
{
    const float* x_num  = (const float*)d_in[0];
    const float* cand_x = (const float*)d_in[1];
    const float* cand_y = (const float*)d_in[2];
    int off = (n_in >= 27) ? 1 : 0;
    int i = 3 + off;
    const float* W_in = (const float*)d_in[i++]; const float* b_in = (const float*)d_in[i++];
    const float* We1  = (const float*)d_in[i++]; const float* be1  = (const float*)d_in[i++];
    const float* We2  = (const float*)d_in[i++]; const float* be2  = (const float*)d_in[i++];
    const float* g_m  = (const float*)d_in[i++]; const float* b_m  = (const float*)d_in[i++];
    const float* Ws   = (const float*)d_in[i++]; const float* bs   = (const float*)d_in[i++];
    const float* Wy   = (const float*)d_in[i++]; const float* by   = (const float*)d_in[i++];
    const float* Wt1  = (const float*)d_in[i++];
    const float* Wt2  = (const float*)d_in[i++]; const float* bt2  = (const float*)d_in[i++];
    const float* Wp1  = (const float*)d_in[i++]; const float* bp1  = (const float*)d_in[i++];
    const float* Wp2  = (const float*)d_in[i++]; const float* bp2  = (const float*)d_in[i++];
    const float* g_h  = (const float*)d_in[i++]; const float* b_h  = (const float*)d_in[i++];
    const float* Wh   = (const float*)d_in[i++]; const float* bh   = (const float*)d_in[i++];
    float* out = (float*)d_out;

    cudaFuncSetAttribute(gemm_mma, cudaFuncAttributeMaxDynamicSharedMemorySize, GEMM_SMEM);

    float *h0f, *ckf, *U, *score, *hnneg, *px, *probs;
    int* idxp;
    GETSYM(h0f, g_h0f); GETSYM(ckf, g_ckf); GETSYM(U, g_U); GETSYM(score, g_score);
    GETSYM(hnneg, g_hnneg); GETSYM(px, g_px);
    GETSYM(idxp, g_idx); GETSYM(probs, g_probs);

    bf16 *xh,*xl,*h0h,*h0l,*th,*tl,*lnh,*lnl,*ckh,*ckl;
    bf16 *dh,*dl,*t2h,*t2l,*pxh,*pxl,*pth,*ptl;
    GETSYM(xh, g_xh); GETSYM(xl, g_xl);
    GETSYM(h0h, g_h0h); GETSYM(h0l, g_h0l); GETSYM(th, g_th);  GETSYM(tl, g_tl);
    GETSYM(lnh, g_lnh); GETSYM(lnl, g_lnl); GETSYM(ckh, g_ckh); GETSYM(ckl, g_ckl);
    GETSYM(dh, g_dh); GETSYM(dl, g_dl); GETSYM(t2h, g_t2h); GETSYM(t2l, g_t2l);
    GETSYM(pxh, g_pxh); GETSYM(pxl, g_pxl); GETSYM(pth, g_pth); GETSYM(ptl, g_ptl);

    bf16 *winh,*winl,*we1h,*we1l,*we2h,*we2l,*wsh,*wsl,*wt1h,*wt1l,*wt2h,*wt2l,*wp1h,*wp1l,*wp2h,*wp2l;
    GETSYM(winh, g_winh); GETSYM(winl, g_winl);
    GETSYM(we1h, g_we1h); GETSYM(we1l, g_we1l);
    GETSYM(we2h, g_we2h); GETSYM(we2l, g_we2l);
    GETSYM(wsh, g_wsh);   GETSYM(wsl, g_wsl);
    GETSYM(wt1h, g_wt1h); GETSYM(wt1l, g_wt1l);
    GETSYM(wt2h, g_wt2h); GETSYM(wt2l, g_wt2l);
    GETSYM(wp1h, g_wp1h); GETSYM(wp1l, g_wp1l);
    GETSYM(wp2h, g_wp2h); GETSYM(wp2l, g_wp2l);

    // [0..2] prep
    transpose_group3<<<dim3(512, 3), 128>>>(We1, Wt1, Wp1,
                                            we1h, we1l, wt1h, wt1l, wp1h, wp1l);
    transpose_group5<<<dim3(256, 5), 128>>>(W_in, We2, Ws, Wt2, Wp2,
                                            winh, winl, we2h, we2l, wsh, wsl,
                                            wt2h, wt2l, wp2h, wp2l);
    split_pad96_all<<<NT, 128>>>(cand_x, x_num, xh, xl);

    const int GT = (NT + 127) / 128;     // 790

    // [3..5] combined encode
    gemm_mma<<<dim3(2, GT), 256, GEMM_SMEM>>>(xh, xl, winh, winl, b_in, nullptr,
                                              h0f, h0h, h0l, NT, 256, 128, 4 | 8);
    gemm_mma<<<dim3(4, GT), 256, GEMM_SMEM>>>(h0h, h0l, we1h, we1l, be1, nullptr,
                                              nullptr, th, tl, NT, 512, 256, 1 | 8);
    gemm_mma<<<dim3(2, GT), 256, GEMM_SMEM>>>(th, tl, we2h, we2l, be2, h0f,
                                              h0f, nullptr, nullptr, NT, 256, 512, 2 | 4);
    ln_split<<<NT, 256>>>(h0f, g_m, b_m, lnh, lnl);
    gemm_mma<<<dim3(2, GT), 256, GEMM_SMEM>>>(lnh, lnl, wsh, wsl, bs, nullptr,
                                              ckf, ckh, ckl, NT, 256, 256, 4 | 8);
    halfnorm_neg<<<NCAND, 256>>>(ckf, hnneg);

    // similarity scores
    gemm_mma<<<dim3(782, 8), 256, GEMM_SMEM>>>(
        ckh + (size_t)NCAND * DM, ckl + (size_t)NCAND * DM, ckh, ckl, hnneg, nullptr,
        score, nullptr, nullptr, BQ, NCAND, 256, 4);

    topk_softmax_kernel<<<BQ, 256>>>(score, NCAND, idxp, probs);
    build_d_split<<<RN, 256>>>(ckf, idxp, dh, dl);

    // value MLP
    gemm_mma<<<dim3(4, 768), 256, GEMM_SMEM>>>(dh, dl, wt1h, wt1l, nullptr, nullptr,
                                               nullptr, t2h, t2l, RN, 512, 256, 1 | 8);
    gemm_mma<<<dim3(2, 768), 256, GEMM_SMEM>>>(t2h, t2l, wt2h, wt2l, nullptr, nullptr,
                                               U, nullptr, nullptr, RN, 256, 512, 4);

    combine_kernel<<<BQ, 256>>>(h0f, U, probs, idxp, cand_y, Wy, by, bt2, px, pxh, pxl);

    // predictor + head
    gemm_mma<<<dim3(4, 8), 256, GEMM_SMEM>>>(pxh, pxl, wp1h, wp1l, bp1, nullptr,
                                             nullptr, pth, ptl, BQ, 512, 256, 1 | 8);
    gemm_mma<<<dim3(2, 8), 256, GEMM_SMEM>>>(pth, ptl, wp2h, wp2l, bp2, px,
                                             px, nullptr, nullptr, BQ, 256, 512, 2 | 4);
    head_kernel<<<BQ, 256>>>(px, g_h, b_h, Wh, bh, out);

    (void)in_sizes; (void)out_size;
}